// round 12
// baseline (speedup 1.0000x reference)
#include <cuda_runtime.h>
#include <cuda_bf16.h>
#include <math.h>

// ---------------------------------------------------------------------------
// ELMo embeddings, fp32. Persistent recurrence, ONE grid barrier per step:
// phase2 uses block-local a through the block's Wp row-slice + atomic
// accumulation; every block finalizes the full h locally.
// ---------------------------------------------------------------------------

namespace {
constexpr int Bn = 8;     // batch
constexpr int Tn = 96;    // time
constexpr int En = 256;   // embed dim
constexpr int Hn = 2048;  // hidden
constexpr int Pn = 256;   // projection
constexpr int Gn = 8192;  // 4*H
constexpr int NBLK = 128; // persistent grid (2 dirs x 64)
constexpr int DBLK = 64;  // blocks per direction
}

// scratch (device globals; allocation-free)
__device__ float g_emb[Bn * Tn * En];
__device__ float g_y0[2][Bn * Tn * Pn];
__device__ float g_y1[2][Bn * Tn * Pn];
__device__ float g_xW[2][(size_t)Tn * Bn * Gn];  // x@Wk+b, step-major
__device__ float g_hacc[3][2][Bn * Pn];          // rotating h partial-sum bufs
__device__ float g_mean[3][Bn];
__device__ float g_var[3][Bn];

// per-direction barrier state (monotonic; never reset -> graph-replay safe)
__device__ unsigned g_cnt[2];
__device__ unsigned g_flag[2];

// ---------------------------------------------------------------------------
__global__ void k_embed(const int* __restrict__ tok, const float* __restrict__ tab) {
    int i = blockIdx.x * 256 + threadIdx.x;  // B*T*E = 196608
    int bt = i >> 8;
    int e = i & 255;
    g_emb[i] = tab[(size_t)tok[bt] * En + e];
}

__global__ void k_zero_acc() {
    int i = blockIdx.x * 256 + threadIdx.x;  // 3*2*2048 = 12288
    (&g_hacc[0][0][0])[i] = 0.f;
}

// ---------------------------------------------------------------------------
// xW GEMM (R9 scalar version, measured at the FFMA issue floor).
// M=768 (s,b), N=8192, K=256. BM=128 BN=128 BK=16, 256 thr, 8x8 microtile.
// ---------------------------------------------------------------------------
__global__ void __launch_bounds__(256, 2)
k_xw(const float* __restrict__ Wk, const float* __restrict__ bias, int layer) {
    const int d = blockIdx.z;
    const int widx = d * 2 + layer;
    const float* __restrict__ x = (layer == 0) ? g_emb : g_y0[d];
    const float* __restrict__ W = Wk + (size_t)widx * En * Gn;
    const float* __restrict__ bi = bias + (size_t)widx * Gn;
    float* __restrict__ out = g_xW[d];
    const int n0 = blockIdx.x * 128;
    const int m0 = blockIdx.y * 128;
    const bool rev = (d == 1);
    const int tid = threadIdx.x;
    const int tx = tid & 15;   // 8 n cols at tx*8
    const int ty = tid >> 4;   // 8 m rows at ty*8

    __shared__ float As[16][132];  // [k][m]
    __shared__ float Bs[16][128];  // [k][n]

    float acc[8][8];
#pragma unroll
    for (int i = 0; i < 8; ++i)
#pragma unroll
        for (int j = 0; j < 8; ++j) acc[i][j] = 0.f;

    // A loader: row ml, 8 k at kl
    const int ml = tid >> 1;
    const int kl = (tid & 1) * 8;
    const int m = m0 + ml;
    const int sA = m >> 3, bA = m & 7;
    const int tA = rev ? (Tn - 1 - sA) : sA;
    const float* xrow = x + (size_t)(bA * Tn + tA) * En;

    // B loader: k row kb, 8 n at nb
    const int kb = tid >> 4;
    const int nb = (tid & 15) * 8;

    for (int k0 = 0; k0 < En; k0 += 16) {
        {
            float4 v0 = *(const float4*)(xrow + k0 + kl);
            float4 v1 = *(const float4*)(xrow + k0 + kl + 4);
            As[kl + 0][ml] = v0.x;
            As[kl + 1][ml] = v0.y;
            As[kl + 2][ml] = v0.z;
            As[kl + 3][ml] = v0.w;
            As[kl + 4][ml] = v1.x;
            As[kl + 5][ml] = v1.y;
            As[kl + 6][ml] = v1.z;
            As[kl + 7][ml] = v1.w;
            const float* wr = W + (size_t)(k0 + kb) * Gn + n0 + nb;
            *(float4*)(&Bs[kb][nb]) = *(const float4*)(wr);
            *(float4*)(&Bs[kb][nb + 4]) = *(const float4*)(wr + 4);
        }
        __syncthreads();
#pragma unroll
        for (int k = 0; k < 16; ++k) {
            float4 a0 = *(const float4*)(&As[k][ty * 8]);
            float4 a1 = *(const float4*)(&As[k][ty * 8 + 4]);
            float4 b0 = *(const float4*)(&Bs[k][tx * 8]);
            float4 b1 = *(const float4*)(&Bs[k][tx * 8 + 4]);
            float av[8] = {a0.x, a0.y, a0.z, a0.w, a1.x, a1.y, a1.z, a1.w};
            float bv[8] = {b0.x, b0.y, b0.z, b0.w, b1.x, b1.y, b1.z, b1.w};
#pragma unroll
            for (int i = 0; i < 8; ++i)
#pragma unroll
                for (int j = 0; j < 8; ++j) acc[i][j] += av[i] * bv[j];
        }
        __syncthreads();
    }
    float4 bva = *(const float4*)(bi + n0 + tx * 8);
    float4 bvb = *(const float4*)(bi + n0 + tx * 8 + 4);
#pragma unroll
    for (int i = 0; i < 8; ++i) {
        int mm = m0 + ty * 8 + i;
        float* op = out + (size_t)mm * Gn + n0 + tx * 8;
        *(float4*)(op) = make_float4(acc[i][0] + bva.x, acc[i][1] + bva.y,
                                     acc[i][2] + bva.z, acc[i][3] + bva.w);
        *(float4*)(op + 4) = make_float4(acc[i][4] + bvb.x, acc[i][5] + bvb.y,
                                         acc[i][6] + bvb.z, acc[i][7] + bvb.w);
    }
}

// ---------------------------------------------------------------------------
// Persistent LSTM recurrence. 128 blocks x 512 threads, 1 block/SM.
// Block bx: dir d = bx>>6, slice q = bx&63 -> units U0=q*32.
// ONE grid barrier per step; h maintained locally in every block.
// ---------------------------------------------------------------------------
__device__ __forceinline__ float fsig(float x) {
    return __fdividef(1.f, 1.f + __expf(-x));
}
__device__ __forceinline__ float ftanh(float x) {
    return __fdividef(2.f, 1.f + __expf(-2.f * x)) - 1.f;
}

__device__ __forceinline__ void dir_barrier(int d, unsigned target, int tid) {
    __threadfence();          // make this thread's REDs/stores visible
    __syncthreads();
    if (tid == 0) {
        unsigned old = atomicAdd(&g_cnt[d], 1u);
        if (old + 1u == target)
            *((volatile unsigned*)&g_flag[d]) = target;
        while ((int)(*((volatile unsigned*)&g_flag[d]) - target) < 0) {}
    }
    __syncthreads();
    __threadfence();
}

// SMEM float offsets
namespace {
constexpr int OF_WR = 0;       // [256][128] (k*128+lc), lc = gate*32+u
constexpr int OF_WP = 32768;   // [32][256]  (klocal*256+p)
constexpr int OF_HT = 40960;   // [256][8]   (p*8+b) current h (block-local)
constexpr int OF_ZP = 43008;   // [8][8][128] (kc*1024 + b*128 + lc)
constexpr int OF_Z  = 51200;   // [8][128]
constexpr int OF_C  = 52224;   // [8][32]
constexpr int OF_A  = 52480;   // [8][32]
constexpr int SM_FLOATS = 52736;  // 210944 B
}

__global__ void __launch_bounds__(512, 1)
k_recur(const float* __restrict__ Wr, const float* __restrict__ Wp,
        const float* __restrict__ mask, int layer) {
    extern __shared__ float sm[];
    float* Wr_sm = sm + OF_WR;
    float* Wp_sm = sm + OF_WP;
    float* hT    = sm + OF_HT;
    float* zpart = sm + OF_ZP;
    float* z_sm  = sm + OF_Z;
    float* c_sm  = sm + OF_C;
    float* a_sm  = sm + OF_A;

    const int tid = threadIdx.x;
    const int bx = blockIdx.x;
    const int d = bx >> 6;
    const int q = bx & 63;
    const int U0 = q * 32;
    const int widx = d * 2 + layer;

    // ---- preload weights ----
    {
        const float* Wg = Wr + (size_t)widx * Pn * Gn;
        for (int i = tid; i < 256 * 128; i += 512) {
            int k = i >> 7, lc = i & 127;
            int gate = lc >> 5, u = lc & 31;
            Wr_sm[i] = __ldg(&Wg[(size_t)k * Gn + gate * Hn + U0 + u]);
        }
        // Wp rows U0..U0+31, all 256 cols: Wp_sm[klocal][p]
        const float* Wpg = Wp + (size_t)widx * Hn * Pn + (size_t)U0 * Pn;
        for (int i = tid; i < 32 * 64; i += 512) {   // float4 granules
            int kr = i >> 6, p4 = i & 63;
            *(float4*)&Wp_sm[kr * 256 + p4 * 4] =
                __ldg((const float4*)&Wpg[kr * Pn + p4 * 4]);
        }
    }
    for (int i = tid; i < Bn * Pn; i += 512) hT[i] = 0.f;
    if (tid < 256) c_sm[tid] = 0.f;

    const unsigned base = *((volatile unsigned*)&g_flag[d]);
    unsigned target = base;
    float* __restrict__ yb = (layer == 0) ? g_y0[d] : g_y1[d];
    const float* __restrict__ xWd = g_xW[d];
    __syncthreads();

    // role indices
    const int kc = tid >> 5;          // phase1 (tid<256): k-chunk
    const int cg = tid & 31;          // phase1: 4-col group
    const int rb = tid >> 6;          // reduce/phase2/finalize: batch
    const int l2 = (tid & 63) * 2;    // reduce: 2 cols
    const int rgate = l2 >> 5, ru = l2 & 31;
    const int pg = tid & 63;          // phase2/finalize: 4 p at pg*4

    for (int s = 0; s < Tn; ++s) {
        const int t = d ? (Tn - 1 - s) : s;
        const int bi = s % 3;
        float* __restrict__ acc_buf = g_hacc[bi][d];

        // prefetch xW for the reduce stage (hides DRAM behind phase1)
        float2 xwv = __ldcg((const float2*)&xWd[((size_t)s * Bn + rb) * Gn +
                                                rgate * Hn + U0 + ru]);

        // ---- phase 1: z partials = h @ Wr (8 k-chunks of 32) ----
        if (tid < 256) {
            float acc[8][4];
#pragma unroll
            for (int b = 0; b < 8; ++b)
                acc[b][0] = acc[b][1] = acc[b][2] = acc[b][3] = 0.f;
            const float* wr0 = Wr_sm + cg * 4;
            const int ke = kc * 32 + 32;
#pragma unroll 4
            for (int k = kc * 32; k < ke; ++k) {
                float4 wv = *(const float4*)(wr0 + k * 128);
                float h8[8];
                *(float4*)(h8) = *(const float4*)(hT + k * 8);
                *(float4*)(h8 + 4) = *(const float4*)(hT + k * 8 + 4);
#pragma unroll
                for (int b = 0; b < 8; ++b) {
                    acc[b][0] += wv.x * h8[b];
                    acc[b][1] += wv.y * h8[b];
                    acc[b][2] += wv.z * h8[b];
                    acc[b][3] += wv.w * h8[b];
                }
            }
#pragma unroll
            for (int b = 0; b < 8; ++b)
                *(float4*)(zpart + kc * 1024 + b * 128 + cg * 4) =
                    make_float4(acc[b][0], acc[b][1], acc[b][2], acc[b][3]);
        }
        __syncthreads();

        // ---- reduce k-chunks + add xW ----
        {
            float z0 = xwv.x, z1 = xwv.y;
#pragma unroll
            for (int kk = 0; kk < 8; ++kk) {
                float2 p = *(const float2*)(zpart + kk * 1024 + rb * 128 + l2);
                z0 += p.x;
                z1 += p.y;
            }
            *(float2*)(z_sm + rb * 128 + l2) = make_float2(z0, z1);
        }
        __syncthreads();

        // ---- gates / cell / a (a stays in SMEM) ----
        if (tid < 256) {
            const int b2 = tid >> 5, u = tid & 31;
            float zi = z_sm[b2 * 128 + u];
            float zf = z_sm[b2 * 128 + 32 + u];
            float zg = z_sm[b2 * 128 + 64 + u];
            float zo = z_sm[b2 * 128 + 96 + u];
            float ig = fsig(zi), fg = fsig(zf), gg = ftanh(zg), og = fsig(zo);
            float cold = c_sm[tid];
            float cn = fminf(3.f, fmaxf(-3.f, fg * cold + ig * gg));
            float mt = __ldg(&mask[b2 * Tn + t]);
            c_sm[tid] = (mt > 0.f) ? cn : cold;
            a_sm[tid] = og * ftanh(cn);
        }
        __syncthreads();

        // ---- phase 2: partial h = a_local @ Wp_slice, atomic-accumulate ----
        {
            float p0 = 0.f, p1 = 0.f, p2 = 0.f, p3 = 0.f;
            const float* arow = a_sm + rb * 32;
            const float* wp = Wp_sm + pg * 4;
#pragma unroll 4
            for (int k = 0; k < 32; ++k) {
                float av = arow[k];
                float4 wv = *(const float4*)(wp + k * 256);
                p0 += av * wv.x;
                p1 += av * wv.y;
                p2 += av * wv.z;
                p3 += av * wv.w;
            }
            float* dst = acc_buf + rb * 256 + pg * 4;
            atomicAdd(dst + 0, p0);
            atomicAdd(dst + 1, p1);
            atomicAdd(dst + 2, p2);
            atomicAdd(dst + 3, p3);
        }

        target += DBLK;
        dir_barrier(d, target, tid);

        // ---- finalize: every block computes full h locally ----
        {
            float4 sum = __ldcg((const float4*)(acc_buf + rb * 256 + pg * 4));
            float mt = __ldg(&mask[rb * Tn + t]);
            float hv[4] = {sum.x, sum.y, sum.z, sum.w};
            float outv[4];
#pragma unroll
            for (int j = 0; j < 4; ++j) {
                int p = pg * 4 + j;
                float old = hT[p * 8 + rb];
                float hn = fminf(3.f, fmaxf(-3.f, hv[j]));
                float v = (mt > 0.f) ? hn : old;
                hT[p * 8 + rb] = v;
                outv[j] = v;
            }
            if (pg == q) {
                *(float4*)&yb[((size_t)rb * Tn + t) * Pn + q * 4] =
                    make_float4(outv[0], outv[1], outv[2], outv[3]);
            }
            // zero the (s+2)%3 buffer slice this block owns
            if (tid < 8) {
                float* zb = g_hacc[(s + 2) % 3][d] + q * 32;
                __stcg((float4*)zb + tid, make_float4(0.f, 0.f, 0.f, 0.f));
            }
        }
        __syncthreads();
    }
}

// ---------------------------------------------------------------------------
// Epilogue (unchanged)
// ---------------------------------------------------------------------------
__device__ __forceinline__ float layer_val(int l, int b, int t, int ch) {
    if (l == 0) return g_emb[(size_t)(b * Tn + t) * En + (ch & 255)];
    const int dd = ch >> 8;
    const size_t idx = (size_t)(b * Tn + t) * Pn + (ch & 255);
    float v = g_y0[dd][idx];
    if (l == 2) v += g_y1[dd][idx];
    return v;
}

__global__ void k_stats(const float* __restrict__ mask) {
    const int b = blockIdx.x;
    const int l = blockIdx.y;
    __shared__ float red[256];
    const int tid = threadIdx.x;

    float nm = 0.f;
    for (int t = tid; t < Tn; t += 256) nm += mask[b * Tn + t];
    red[tid] = nm;
    __syncthreads();
    for (int st = 128; st > 0; st >>= 1) {
        if (tid < st) red[tid] += red[tid + st];
        __syncthreads();
    }
    const float num = red[0];
    __syncthreads();

    float smv = 0.f;
    for (int i = tid; i < Tn * 512; i += 256) {
        int t = i >> 9, ch = i & 511;
        smv += layer_val(l, b, t, ch) * mask[b * Tn + t];
    }
    red[tid] = smv;
    __syncthreads();
    for (int st = 128; st > 0; st >>= 1) {
        if (tid < st) red[tid] += red[tid + st];
        __syncthreads();
    }
    const float mean = red[0] / num;
    __syncthreads();

    float vs = 0.f;
    for (int i = tid; i < Tn * 512; i += 256) {
        int t = i >> 9, ch = i & 511;
        float m = mask[b * Tn + t];
        float dd = (layer_val(l, b, t, ch) * m - mean) * m;
        vs += dd * dd;
    }
    red[tid] = vs;
    __syncthreads();
    for (int st = 128; st > 0; st >>= 1) {
        if (tid < st) red[tid] += red[tid + st];
        __syncthreads();
    }
    if (tid == 0) {
        g_mean[l][b] = mean;
        g_var[l][b] = red[0] / num;
    }
}

__global__ void k_final(const float* __restrict__ elmo_w, const float* __restrict__ gamma,
                        float* __restrict__ out) {
    const int i = blockIdx.x * 256 + threadIdx.x;
    const int ch = i & 511;
    const int bt = i >> 9;
    const int b = bt / Tn;
    const int t = bt - b * Tn;
    float w0 = elmo_w[0], w1 = elmo_w[1], w2 = elmo_w[2];
    float mx = fmaxf(w0, fmaxf(w1, w2));
    float e0 = expf(w0 - mx), e1 = expf(w1 - mx), e2 = expf(w2 - mx);
    float inv = 1.f / (e0 + e1 + e2);
    float gm = gamma[0];
    float r = 0.f;
    r += e0 * inv * (layer_val(0, b, t, ch) - g_mean[0][b]) / sqrtf(g_var[0][b] + 1e-12f);
    r += e1 * inv * (layer_val(1, b, t, ch) - g_mean[1][b]) / sqrtf(g_var[1][b] + 1e-12f);
    r += e2 * inv * (layer_val(2, b, t, ch) - g_mean[2][b]) / sqrtf(g_var[2][b] + 1e-12f);
    out[i] = gm * r;
}

// ---------------------------------------------------------------------------
extern "C" void kernel_launch(void* const* d_in, const int* in_sizes, int n_in,
                              void* d_out, int out_size) {
    (void)in_sizes; (void)n_in; (void)out_size;
    const int*   tokens = (const int*)d_in[0];
    const float* mask   = (const float*)d_in[1];
    const float* table  = (const float*)d_in[2];
    const float* Wk     = (const float*)d_in[3];
    const float* Wr     = (const float*)d_in[4];
    const float* bias   = (const float*)d_in[5];
    const float* Wp     = (const float*)d_in[6];
    const float* elmo_w = (const float*)d_in[7];
    const float* gamma  = (const float*)d_in[8];
    float* out = (float*)d_out;

    const int recur_smem = SM_FLOATS * 4;  // 210944 B
    cudaFuncSetAttribute(k_recur, cudaFuncAttributeMaxDynamicSharedMemorySize,
                         recur_smem);

    k_embed<<<768, 256>>>(tokens, table);
    for (int layer = 0; layer < 2; ++layer) {
        k_zero_acc<<<48, 256>>>();
        k_xw<<<dim3(Gn / 128, (Tn * Bn) / 128, 2), 256>>>(Wk, bias, layer);
        k_recur<<<NBLK, 512, recur_smem>>>(Wr, Wp, mask, layer);
    }
    k_stats<<<dim3(8, 3), 256>>>(mask);
    k_final<<<1536, 256>>>(elmo_w, gamma, out);
}